// round 15
// baseline (speedup 1.0000x reference)
#include <cuda_runtime.h>
#include <cuda_fp16.h>

// ---------------------------------------------------------------------------
// SplatterPhongShader: N=4, H=256, W=256, K=4 — fused single kernel.
// Block = 16x16 output tile (halo 18x18). Shade writes per-element:
//   sP = float4 (rgb0, rgb1, rgb2, 1.0f)   -> BOTH f32x2 FMA pairs aligned
//   sQ = uint4  (fy0fy1, fy2fx0, fx1fx2, 0) -> one LDS.128 for all factors
// Blend: 3x3 gather, FMNMX argmin, T/F/S f32x2 buckets, B = T - F - S.
// Operating point: 64 regs, 4 blocks/SM, 46.7KB smem/block.
// ---------------------------------------------------------------------------

namespace cfg {
constexpr int NB = 4, HH = 256, WW = 256, KK = 4;
// (1+0.05) / (1 + 4*exp(-2) + 4*exp(-4))
constexpr float NORM_C = 0.6503143832f;
constexpr int TW = 16, TH = 16;            // output tile
constexpr int HR = 18, HC = 18;            // halo rows/cols (tile + 1 ring)
constexpr int HPIX = HR * HC;              // 324 halo pixels
}

static __device__ __forceinline__ unsigned pack2(float a, float b) {
    __half2 h = __floats2half2_rn(a, b);
    return *reinterpret_cast<unsigned*>(&h);
}
static __device__ __forceinline__ float lo_h(unsigned u) {
    return __half2float(__ushort_as_half((unsigned short)(u & 0xffffu)));
}
static __device__ __forceinline__ float hi_h(unsigned u) {
    return __half2float(__ushort_as_half((unsigned short)(u >> 16)));
}
static __device__ __forceinline__ __half lo_hh(unsigned u) {
    return __ushort_as_half((unsigned short)(u & 0xffffu));
}
static __device__ __forceinline__ __half hi_hh(unsigned u) {
    return __ushort_as_half((unsigned short)(u >> 16));
}

// ---- packed f32x2 helpers (Blackwell dual-lane FMA; PTX-only) ----
static __device__ __forceinline__ unsigned long long packf2(float lo, float hi) {
    unsigned long long r;
    asm("mov.b64 %0, {%1, %2};" : "=l"(r) : "f"(lo), "f"(hi));
    return r;
}
static __device__ __forceinline__ void fma2(unsigned long long& acc,
                                            unsigned long long ab,
                                            unsigned long long w2) {
    asm("fma.rn.f32x2 %0, %1, %2, %0;" : "+l"(acc) : "l"(ab), "l"(w2));
}
static __device__ __forceinline__ void unpackf2(unsigned long long v,
                                                float& lo, float& hi) {
    asm("mov.b64 {%0, %1}, %2;" : "=f"(lo), "=f"(hi) : "l"(v));
}

// ---------------------------------------------------------------------------
__global__ __launch_bounds__(256, 4)
void fused_kernel(const float* __restrict__ texels,
                  const float* __restrict__ normals,
                  const float* __restrict__ pcam,
                  const float* __restrict__ screen,
                  const float* __restrict__ qdepth,
                  const void*  __restrict__ mask,
                  const float* __restrict__ Lp,
                  const float* __restrict__ la,
                  const float* __restrict__ ld,
                  const float* __restrict__ ls,
                  const float* __restrict__ Cp,
                  const float* __restrict__ ma,
                  const float* __restrict__ md,
                  const float* __restrict__ ms,
                  float* __restrict__ out)
{
    __shared__ float4 sQd[cfg::HPIX];               //  5,184 B
    __shared__ float4 sP [cfg::KK][cfg::HPIX];      // 20,736 B
    __shared__ uint4  sQ [cfg::KK][cfg::HPIX];      // 20,736 B (46,656 B)

    const int tid = threadIdx.x;
    const int tx = tid & 15;         // 0..15
    const int ty = tid >> 4;         // 0..15
    const int x0 = blockIdx.x * cfg::TW;
    const int y0 = blockIdx.y * cfg::TH;
    const int n  = blockIdx.z;

    const float4* __restrict__ q4 = reinterpret_cast<const float4*>(qdepth);
    const float4* __restrict__ t4 = reinterpret_cast<const float4*>(texels);
    const float4* __restrict__ n4 = reinterpret_cast<const float4*>(normals);
    const float4* __restrict__ p4 = reinterpret_cast<const float4*>(pcam);
    const float4* __restrict__ s4 = reinterpret_cast<const float4*>(screen);

    // ---- mask dtype probe (warp-uniform; first 256 words, L1/L2 hits) ----
    const int lid = tid & 31;
    const uint4* mw = (const uint4*)mask;
    uint4 v0 = mw[lid * 2];
    uint4 v1 = mw[lid * 2 + 1];
    unsigned sawword = 0u, sawbyte = 0u;
    {
        const unsigned ws[8] = {v0.x, v0.y, v0.z, v0.w, v1.x, v1.y, v1.z, v1.w};
#pragma unroll
        for (int t = 0; t < 8; ++t) {
            unsigned w = ws[t];
            if (w == 1u || w == 0x3f800000u) sawword = 1u;
            else if (w > 1u) sawbyte = 1u;
        }
    }
    sawword = __ballot_sync(0xffffffffu, sawword);
    sawbyte = __ballot_sync(0xffffffffu, sawbyte);
    const bool byte_layout = (sawbyte != 0u) && (sawword == 0u);

    // ---- uniform lighting constants ----
    const float amb0 = la[0]*ma[0], amb1 = la[1]*ma[1], amb2 = la[2]*ma[2];
    const float dif0 = ld[0]*md[0], dif1 = ld[1]*md[1], dif2 = ld[2]*md[2];
    const float spc0 = ls[0]*ms[0], spc1 = ls[1]*ms[1], spc2 = ls[2]*ms[2];
    const float Lx = Lp[0], Ly = Lp[1], Lz = Lp[2];
    const float Cx = Cp[0], Cy = Cp[1], Cz = Cp[2];

    // ---- shade halo: one PIXEL (4 layers) per thread-iteration ----
    for (int hp = tid; hp < cfg::HPIX; hp += 256) {
        const int r = hp / cfg::HC, c = hp % cfg::HC;
        const int gy = y0 - 1 + r, gx = x0 - 1 + c;
        const bool ok = ((unsigned)gy < (unsigned)cfg::HH) &&
                        ((unsigned)gx < (unsigned)cfg::WW);
        if (!ok) {
            sQd[hp] = make_float4(1e9f, 1e9f, 1e9f, 1e9f);
#pragma unroll
            for (int kk = 0; kk < 4; ++kk) {
                sP[kk][hp] = make_float4(0.f, 0.f, 0.f, 1.0f);
                sQ[kk][hp] = make_uint4(0u, 0u, 0u, 0u);
            }
            continue;
        }
        const int pg = (n * cfg::HH + gy) * cfg::WW + gx;

        sQd[hp] = q4[pg];

        // vectorized per-pixel loads (all 16B-aligned)
        const float4 T0 = t4[pg*3+0], T1 = t4[pg*3+1], T2 = t4[pg*3+2];
        const float4 N0 = n4[pg*3+0], N1 = n4[pg*3+1], N2 = n4[pg*3+2];
        const float4 P0 = p4[pg*3+0], P1 = p4[pg*3+1], P2 = p4[pg*3+2];
        const float4 S0 = s4[pg*2+0], S1 = s4[pg*2+1];

        float alphav[4];
        if (byte_layout) {
            const unsigned mb = ((const unsigned*)mask)[pg];
#pragma unroll
            for (int kk = 0; kk < 4; ++kk)
                alphav[kk] = ((mb >> (8*kk)) & 0xffu) ? 0.0f : 1.0f;
        } else {
            const uint4 mq = ((const uint4*)mask)[pg];
            alphav[0] = mq.x ? 0.0f : 1.0f;
            alphav[1] = mq.y ? 0.0f : 1.0f;
            alphav[2] = mq.z ? 0.0f : 1.0f;
            alphav[3] = mq.w ? 0.0f : 1.0f;
        }

        const float tt[12] = {T0.x,T0.y,T0.z,T0.w, T1.x,T1.y,T1.z,T1.w,
                              T2.x,T2.y,T2.z,T2.w};
        const float nn[12] = {N0.x,N0.y,N0.z,N0.w, N1.x,N1.y,N1.z,N1.w,
                              N2.x,N2.y,N2.z,N2.w};
        const float pp[12] = {P0.x,P0.y,P0.z,P0.w, P1.x,P1.y,P1.z,P1.w,
                              P2.x,P2.y,P2.z,P2.w};
        const float ss[8]  = {S0.x,S0.y,S0.z,S0.w, S1.x,S1.y,S1.z,S1.w};

#pragma unroll
        for (int kk = 0; kk < 4; ++kk) {
            const float t0 = tt[3*kk+0], t1 = tt[3*kk+1], t2 = tt[3*kk+2];
            float nx = nn[3*kk+0], ny = nn[3*kk+1], nz = nn[3*kk+2];
            const float px = pp[3*kk+0], py = pp[3*kk+1], pz = pp[3*kk+2];

            float rin = rsqrtf(nx*nx + ny*ny + nz*nz + 1e-8f);
            nx *= rin; ny *= rin; nz *= rin;

            float lxx = Lx - px, lyy = Ly - py, lzz = Lz - pz;
            float ril = rsqrtf(lxx*lxx + lyy*lyy + lzz*lzz + 1e-8f);
            lxx *= ril; lyy *= ril; lzz *= ril;

            float vx = Cx - px, vy = Cy - py, vz = Cz - pz;
            float riv = rsqrtf(vx*vx + vy*vy + vz*vz + 1e-8f);
            vx *= riv; vy *= riv; vz *= riv;

            const float ndl = nx*lxx + ny*lyy + nz*lzz;
            const float tn = 2.0f * ndl;
            const float rx = tn*nx - lxx, ry = tn*ny - lyy, rz = tn*nz - lzz;
            float rdv = fmaxf(rx*vx + ry*vy + rz*vz, 0.0f);

            float s = rdv*rdv;  s = s*s;  s = s*s;  s = s*s;  s = s*s;  s = s*s;

            const float relndl = fmaxf(ndl, 0.0f);
            const float rgb0 = t0 * (amb0 + dif0*relndl) + spc0*s;
            const float rgb1 = t1 * (amb1 + dif1*relndl) + spc1*s;
            const float rgb2 = t2 * (amb2 + dif2*relndl) + spc2*s;

            const float jy = ss[2*kk+0] - ((float)gy + 0.5f);
            const float jx = ss[2*kk+1] - ((float)gx + 0.5f);
            const float na = cfg::NORM_C * alphav[kk];

            const float fy0 = __expf(-2.0f * (jy + 1.0f) * (jy + 1.0f)) * na;
            const float fy1 = __expf(-2.0f *  jy         *  jy        ) * na;
            const float fy2 = __expf(-2.0f * (jy - 1.0f) * (jy - 1.0f)) * na;
            const float fx0 = __expf(-2.0f * (jx + 1.0f) * (jx + 1.0f));
            const float fx1 = __expf(-2.0f *  jx         *  jx        );
            const float fx2 = __expf(-2.0f * (jx - 1.0f) * (jx - 1.0f));

            sP[kk][hp] = make_float4(rgb0, rgb1, rgb2, 1.0f);
            sQ[kk][hp] = make_uint4(pack2(fy0, fy1), pack2(fy2, fx0),
                                    pack2(fx1, fx2), 0u);
        }
    }
    __syncthreads();

    // ---- per-pixel gather; T/F/S accumulation, B = T - F - S ----
    const float4 qo = sQd[(ty + 1) * cfg::HC + (tx + 1)];
    const float q0 = qo.x;

    unsigned long long T01 = 0ull, T2w = 0ull;
    unsigned long long F01 = 0ull, F2w = 0ull;
    unsigned long long S01 = 0ull, S2w = 0ull;

#pragma unroll
    for (int dyy = 0; dyy < 3; ++dyy) {
#pragma unroll
        for (int dxx = 0; dxx < 3; ++dxx) {
            const int bidx = (ty + dyy) * cfg::HC + (tx + dxx);
            const float4 pq = sQd[bidx];
            const float ptop = pq.x;

            // FMNMX-tree argmin (first-index tie-break = argmin)
            const float dq0 = fabsf(ptop - qo.x);
            const float dq1 = fabsf(ptop - qo.y);
            const float dq2 = fabsf(ptop - qo.z);
            const float dq3 = fabsf(ptop - qo.w);
            const float dqm = fminf(fminf(dq0, dq1), fminf(dq2, dq3));
            const int lq = (dq0 == dqm) ? 0 : (dq1 == dqm) ? 1
                         : (dq2 == dqm) ? 2 : 3;

            const float dp0 = fabsf(q0 - pq.x);
            const float dp1 = fabsf(q0 - pq.y);
            const float dp2 = fabsf(q0 - pq.z);
            const float dp3 = fabsf(q0 - pq.w);
            const float dpm = fminf(fminf(dp0, dp1), fminf(dp2, dp3));
            const int lp = (dp0 == dpm) ? 0 : (dp1 == dpm) ? 1
                         : (dp2 == dpm) ? 2 : 3;

            // level = kk + occ; no = -occ. F: kk<no, S: kk==no, B: kk>no
            const int no = (dqm <= dpm) ? -lq : lp;

#pragma unroll
            for (int kk = 0; kk < cfg::KK; ++kk) {
                const float4 P  = sP[kk][bidx];       // rgb0,rgb1,rgb2,1.0
                const uint4  Qv = sQ[kk][bidx];
                // fy index 2-dyy: fy0=lo(Qv.x) fy1=hi(Qv.x) fy2=lo(Qv.y)
                const __half fy = (dyy == 0) ? lo_hh(Qv.y)
                                : (dyy == 1) ? hi_hh(Qv.x)
                                             : lo_hh(Qv.x);
                // fx index 2-dxx: fx0=hi(Qv.y) fx1=lo(Qv.z) fx2=hi(Qv.z)
                const __half fx = (dxx == 0) ? hi_hh(Qv.z)
                                : (dxx == 1) ? lo_hh(Qv.z)
                                             : hi_hh(Qv.y);
                const float w = __half2float(__hmul(fy, fx));

                const unsigned long long Pxy = packf2(P.x, P.y);
                const unsigned long long Pz1 = packf2(P.z, P.w);  // (z, 1.0)
                const unsigned long long wT2 = packf2(w, w);

                fma2(T01, Pxy, wT2); fma2(T2w, Pz1, wT2);

                if (kk < 3) {   // kk=3 can never satisfy kk<no (no<=3)
                    const unsigned long long wF2 = (kk < no) ? wT2 : 0ull;
                    fma2(F01, Pxy, wF2); fma2(F2w, Pz1, wF2);
                }
                const unsigned long long wS2 = (kk == no) ? wT2 : 0ull;
                fma2(S01, Pxy, wS2); fma2(S2w, Pz1, wS2);
            }
        }
    }

    float aT0,aT1,aT2,aT3, aF0,aF1,aF2,aF3, aS0,aS1,aS2,aS3;
    unpackf2(T01, aT0, aT1); unpackf2(T2w, aT2, aT3);
    unpackf2(F01, aF0, aF1); unpackf2(F2w, aF2, aF3);
    unpackf2(S01, aS0, aS1); unpackf2(S2w, aS2, aS3);

    float aB0 = aT0 - aF0 - aS0;
    float aB1 = aT1 - aF1 - aS1;
    float aB2 = aT2 - aF2 - aS2;
    float aB3 = aT3 - aF3 - aS3;
    // true nonzero bucket weights are >= ~7e-5; subtraction residue <= ~2e-6.
    if (aB3 < 1e-5f) { aB0 = 0.f; aB1 = 0.f; aB2 = 0.f; aB3 = 0.f; }

    // ---- composite: bg, surface, foreground, then white background ----
    const float ib = __fdividef(1.0f, fmaxf(aB3, 1e-10f));
    float o0 = aB0*ib, o1 = aB1*ib, o2 = aB2*ib, o3 = aB3*ib;

    const float is = __fdividef(1.0f, fmaxf(aS3, 1e-10f));
    {
        const float s0 = aS0*is, s1 = aS1*is, s2 = aS2*is, s3 = aS3*is;
        const float om = 1.0f - s3;
        o0 = s0 + om*o0; o1 = s1 + om*o1; o2 = s2 + om*o2; o3 = s3 + om*o3;
    }
    const float iff = __fdividef(1.0f, fmaxf(aF3, 1e-10f));
    {
        const float f0 = aF0*iff, f1 = aF1*iff, f2 = aF2*iff, f3 = aF3*iff;
        const float om = 1.0f - f3;
        o0 = f0 + om*o0; o1 = f1 + om*o1; o2 = f2 + om*o2; o3 = f3 + om*o3;
    }
    const float bgm = 1.0f - o3;
    const int pix = (n * cfg::HH + (y0 + ty)) * cfg::WW + (x0 + tx);
    reinterpret_cast<float4*>(out)[pix] =
        make_float4(o0 + bgm, o1 + bgm, o2 + bgm, o3);
}

// ---------------------------------------------------------------------------
extern "C" void kernel_launch(void* const* d_in, const int* in_sizes, int n_in,
                              void* d_out, int out_size)
{
    const float* texels  = (const float*)d_in[0];
    const float* normals = (const float*)d_in[1];
    const float* pcam    = (const float*)d_in[2];
    const float* screen  = (const float*)d_in[3];
    const float* qdepth  = (const float*)d_in[4];
    const void*  mask    = d_in[5];
    const float* Lp      = (const float*)d_in[6];
    const float* la      = (const float*)d_in[7];
    const float* ld      = (const float*)d_in[8];
    const float* ls      = (const float*)d_in[9];
    const float* Cp      = (const float*)d_in[10];
    const float* ma      = (const float*)d_in[11];
    const float* md      = (const float*)d_in[12];
    const float* ms      = (const float*)d_in[13];
    float* out = (float*)d_out;

    dim3 blk(256, 1, 1);
    dim3 grd(cfg::WW / cfg::TW, cfg::HH / cfg::TH, cfg::NB);  // 1024 blocks
    fused_kernel<<<grd, blk>>>(texels, normals, pcam, screen, qdepth, mask,
                               Lp, la, ld, ls, Cp, ma, md, ms, out);
}

// round 16
// speedup vs baseline: 1.1764x; 1.1764x over previous
#include <cuda_runtime.h>
#include <cuda_fp16.h>

// ---------------------------------------------------------------------------
// SplatterPhongShader: N=4, H=256, W=256, K=4 — fused single kernel.
// Block = 16x16 output tile (halo 18x18 = 1.27x shade redundancy, 36.3KB
// smem, 24B/element payload); shades 4 layers/pixel with vectorized float4
// loads into static smem, then 3x3 gather with FMNMX-tree argmin occlusion,
// T/F/S f32x2 bucket accumulation (B = T - F - S), fast-div composite.
// Operating point: 64 regs, 4 blocks/SM (proven optimum).
// ---------------------------------------------------------------------------

namespace cfg {
constexpr int NB = 4, HH = 256, WW = 256, KK = 4;
// (1+0.05) / (1 + 4*exp(-2) + 4*exp(-4))
constexpr float NORM_C = 0.6503143832f;
constexpr int TW = 16, TH = 16;            // output tile
constexpr int HR = 18, HC = 18;            // halo rows/cols (tile + 1 ring)
constexpr int HPIX = HR * HC;              // 324 halo pixels
}

static __device__ __forceinline__ unsigned pack2(float a, float b) {
    __half2 h = __floats2half2_rn(a, b);
    return *reinterpret_cast<unsigned*>(&h);
}

// ---- packed f32x2 helpers (Blackwell dual-lane FMA; PTX-only) ----
static __device__ __forceinline__ unsigned long long packf2(float lo, float hi) {
    unsigned long long r;
    asm("mov.b64 %0, {%1, %2};" : "=l"(r) : "f"(lo), "f"(hi));
    return r;
}
static __device__ __forceinline__ void fma2(unsigned long long& acc,
                                            unsigned long long ab,
                                            unsigned long long w2) {
    asm("fma.rn.f32x2 %0, %1, %2, %0;" : "+l"(acc) : "l"(ab), "l"(w2));
}
static __device__ __forceinline__ void unpackf2(unsigned long long v,
                                                float& lo, float& hi) {
    asm("mov.b64 {%0, %1}, %2;" : "=f"(lo), "=f"(hi) : "l"(v));
}

// ---------------------------------------------------------------------------
__global__ __launch_bounds__(256, 4)
void fused_kernel(const float* __restrict__ texels,
                  const float* __restrict__ normals,
                  const float* __restrict__ pcam,
                  const float* __restrict__ screen,
                  const float* __restrict__ qdepth,
                  const void*  __restrict__ mask,
                  const float* __restrict__ Lp,
                  const float* __restrict__ la,
                  const float* __restrict__ ld,
                  const float* __restrict__ ls,
                  const float* __restrict__ Cp,
                  const float* __restrict__ ma,
                  const float* __restrict__ md,
                  const float* __restrict__ ms,
                  float* __restrict__ out)
{
    __shared__ float4 sQd[cfg::HPIX];               //  5,184 B
    __shared__ float4 sP [cfg::KK][cfg::HPIX];      // 20,736 B
    __shared__ uint2  sQ [cfg::KK][cfg::HPIX];      // 10,368 B (36,288 B)

    const int tid = threadIdx.x;
    const int tx = tid & 15;         // 0..15
    const int ty = tid >> 4;         // 0..15
    const int x0 = blockIdx.x * cfg::TW;
    const int y0 = blockIdx.y * cfg::TH;
    const int n  = blockIdx.z;

    const float4* __restrict__ q4 = reinterpret_cast<const float4*>(qdepth);
    const float4* __restrict__ t4 = reinterpret_cast<const float4*>(texels);
    const float4* __restrict__ n4 = reinterpret_cast<const float4*>(normals);
    const float4* __restrict__ p4 = reinterpret_cast<const float4*>(pcam);
    const float4* __restrict__ s4 = reinterpret_cast<const float4*>(screen);

    // ---- mask dtype probe (warp-uniform; first 256 words, L1/L2 hits) ----
    const int lid = tid & 31;
    const uint4* mw = (const uint4*)mask;
    uint4 v0 = mw[lid * 2];
    uint4 v1 = mw[lid * 2 + 1];
    unsigned sawword = 0u, sawbyte = 0u;
    {
        const unsigned ws[8] = {v0.x, v0.y, v0.z, v0.w, v1.x, v1.y, v1.z, v1.w};
#pragma unroll
        for (int t = 0; t < 8; ++t) {
            unsigned w = ws[t];
            if (w == 1u || w == 0x3f800000u) sawword = 1u;
            else if (w > 1u) sawbyte = 1u;
        }
    }
    sawword = __ballot_sync(0xffffffffu, sawword);
    sawbyte = __ballot_sync(0xffffffffu, sawbyte);
    const bool byte_layout = (sawbyte != 0u) && (sawword == 0u);

    // ---- uniform lighting constants ----
    const float amb0 = la[0]*ma[0], amb1 = la[1]*ma[1], amb2 = la[2]*ma[2];
    const float dif0 = ld[0]*md[0], dif1 = ld[1]*md[1], dif2 = ld[2]*md[2];
    const float spc0 = ls[0]*ms[0], spc1 = ls[1]*ms[1], spc2 = ls[2]*ms[2];
    const float Lx = Lp[0], Ly = Lp[1], Lz = Lp[2];
    const float Cx = Cp[0], Cy = Cp[1], Cz = Cp[2];

    // ---- shade halo: one PIXEL (4 layers) per thread-iteration ----
    for (int hp = tid; hp < cfg::HPIX; hp += 256) {
        const int r = hp / cfg::HC, c = hp % cfg::HC;
        const int gy = y0 - 1 + r, gx = x0 - 1 + c;
        const bool ok = ((unsigned)gy < (unsigned)cfg::HH) &&
                        ((unsigned)gx < (unsigned)cfg::WW);
        if (!ok) {
            sQd[hp] = make_float4(1e9f, 1e9f, 1e9f, 1e9f);
#pragma unroll
            for (int kk = 0; kk < 4; ++kk) {
                sP[kk][hp] = make_float4(0.f, 0.f, 0.f, 0.f);
                sQ[kk][hp] = make_uint2(0u, 0u);
            }
            continue;
        }
        const int pg = (n * cfg::HH + gy) * cfg::WW + gx;

        sQd[hp] = q4[pg];

        // vectorized per-pixel loads (all 16B-aligned)
        const float4 T0 = t4[pg*3+0], T1 = t4[pg*3+1], T2 = t4[pg*3+2];
        const float4 N0 = n4[pg*3+0], N1 = n4[pg*3+1], N2 = n4[pg*3+2];
        const float4 P0 = p4[pg*3+0], P1 = p4[pg*3+1], P2 = p4[pg*3+2];
        const float4 S0 = s4[pg*2+0], S1 = s4[pg*2+1];

        float alphav[4];
        if (byte_layout) {
            const unsigned mb = ((const unsigned*)mask)[pg];
#pragma unroll
            for (int kk = 0; kk < 4; ++kk)
                alphav[kk] = ((mb >> (8*kk)) & 0xffu) ? 0.0f : 1.0f;
        } else {
            const uint4 mq = ((const uint4*)mask)[pg];
            alphav[0] = mq.x ? 0.0f : 1.0f;
            alphav[1] = mq.y ? 0.0f : 1.0f;
            alphav[2] = mq.z ? 0.0f : 1.0f;
            alphav[3] = mq.w ? 0.0f : 1.0f;
        }

        const float tt[12] = {T0.x,T0.y,T0.z,T0.w, T1.x,T1.y,T1.z,T1.w,
                              T2.x,T2.y,T2.z,T2.w};
        const float nn[12] = {N0.x,N0.y,N0.z,N0.w, N1.x,N1.y,N1.z,N1.w,
                              N2.x,N2.y,N2.z,N2.w};
        const float pp[12] = {P0.x,P0.y,P0.z,P0.w, P1.x,P1.y,P1.z,P1.w,
                              P2.x,P2.y,P2.z,P2.w};
        const float ss[8]  = {S0.x,S0.y,S0.z,S0.w, S1.x,S1.y,S1.z,S1.w};

#pragma unroll
        for (int kk = 0; kk < 4; ++kk) {
            const float t0 = tt[3*kk+0], t1 = tt[3*kk+1], t2 = tt[3*kk+2];
            float nx = nn[3*kk+0], ny = nn[3*kk+1], nz = nn[3*kk+2];
            const float px = pp[3*kk+0], py = pp[3*kk+1], pz = pp[3*kk+2];

            float rin = rsqrtf(nx*nx + ny*ny + nz*nz + 1e-8f);
            nx *= rin; ny *= rin; nz *= rin;

            float lxx = Lx - px, lyy = Ly - py, lzz = Lz - pz;
            float ril = rsqrtf(lxx*lxx + lyy*lyy + lzz*lzz + 1e-8f);
            lxx *= ril; lyy *= ril; lzz *= ril;

            float vx = Cx - px, vy = Cy - py, vz = Cz - pz;
            float riv = rsqrtf(vx*vx + vy*vy + vz*vz + 1e-8f);
            vx *= riv; vy *= riv; vz *= riv;

            const float ndl = nx*lxx + ny*lyy + nz*lzz;
            const float tn = 2.0f * ndl;
            const float rx = tn*nx - lxx, ry = tn*ny - lyy, rz = tn*nz - lzz;
            float rdv = fmaxf(rx*vx + ry*vy + rz*vz, 0.0f);

            float s = rdv*rdv;  s = s*s;  s = s*s;  s = s*s;  s = s*s;  s = s*s;

            const float relndl = fmaxf(ndl, 0.0f);
            const float rgb0 = t0 * (amb0 + dif0*relndl) + spc0*s;
            const float rgb1 = t1 * (amb1 + dif1*relndl) + spc1*s;
            const float rgb2 = t2 * (amb2 + dif2*relndl) + spc2*s;

            const float jy = ss[2*kk+0] - ((float)gy + 0.5f);
            const float jx = ss[2*kk+1] - ((float)gx + 0.5f);
            const float na = cfg::NORM_C * alphav[kk];

            const float fy0 = __expf(-2.0f * (jy + 1.0f) * (jy + 1.0f)) * na;
            const float fy1 = __expf(-2.0f *  jy         *  jy        ) * na;
            const float fy2 = __expf(-2.0f * (jy - 1.0f) * (jy - 1.0f)) * na;
            const float fx0 = __expf(-2.0f * (jx + 1.0f) * (jx + 1.0f));
            const float fx1 = __expf(-2.0f *  jx         *  jx        );
            const float fx2 = __expf(-2.0f * (jx - 1.0f) * (jx - 1.0f));

            sP[kk][hp] = make_float4(rgb0, rgb1, rgb2,
                                     __uint_as_float(pack2(fy0, fy1)));
            sQ[kk][hp] = make_uint2(pack2(fy2, fx0), pack2(fx1, fx2));
        }
    }
    __syncthreads();

    // ---- per-pixel gather; T/F/S accumulation, B = T - F - S ----
    const float4 qo = sQd[(ty + 1) * cfg::HC + (tx + 1)];
    const float q0 = qo.x;

    unsigned long long T01 = 0ull, T2w = 0ull;
    unsigned long long F01 = 0ull, F2w = 0ull;
    unsigned long long S01 = 0ull, S2w = 0ull;

#pragma unroll
    for (int dyy = 0; dyy < 3; ++dyy) {
#pragma unroll
        for (int dxx = 0; dxx < 3; ++dxx) {
            const int bidx = (ty + dyy) * cfg::HC + (tx + dxx);
            const float4 pq = sQd[bidx];
            const float ptop = pq.x;

            // FMNMX-tree argmin (first-index tie-break = argmin)
            const float dq0 = fabsf(ptop - qo.x);
            const float dq1 = fabsf(ptop - qo.y);
            const float dq2 = fabsf(ptop - qo.z);
            const float dq3 = fabsf(ptop - qo.w);
            const float dqm = fminf(fminf(dq0, dq1), fminf(dq2, dq3));
            const int lq = (dq0 == dqm) ? 0 : (dq1 == dqm) ? 1
                         : (dq2 == dqm) ? 2 : 3;

            const float dp0 = fabsf(q0 - pq.x);
            const float dp1 = fabsf(q0 - pq.y);
            const float dp2 = fabsf(q0 - pq.z);
            const float dp3 = fabsf(q0 - pq.w);
            const float dpm = fminf(fminf(dp0, dp1), fminf(dp2, dp3));
            const int lp = (dp0 == dpm) ? 0 : (dp1 == dpm) ? 1
                         : (dp2 == dpm) ? 2 : 3;

            // level = kk + occ; no = -occ. F: kk<no, S: kk==no, B: kk>no
            const int no = (dqm <= dpm) ? -lq : lp;

#pragma unroll
            for (int kk = 0; kk < cfg::KK; ++kk) {
                const float4 P  = sP[kk][bidx];
                const uint2  Qv = sQ[kk][bidx];
                const __half2 h01 = *reinterpret_cast<const __half2*>(&P.w);
                const __half2 hx  = *reinterpret_cast<const __half2*>(&Qv.x);
                const __half2 hy  = *reinterpret_cast<const __half2*>(&Qv.y);
                // fy index 2-dyy: fy0=h01.x fy1=h01.y fy2=hx.x
                const __half fy = (dyy == 0) ? hx.x
                                : (dyy == 1) ? h01.y
                                             : h01.x;
                // fx index 2-dxx: fx0=hx.y fx1=hy.x fx2=hy.y
                const __half fx = (dxx == 0) ? hy.y
                                : (dxx == 1) ? hy.x
                                             : hx.y;
                const float w = __half2float(__hmul(fy, fx));

                const unsigned long long Pxy = packf2(P.x, P.y);
                const unsigned long long Pz1 = packf2(P.z, 1.0f);
                const unsigned long long wT2 = packf2(w, w);

                fma2(T01, Pxy, wT2); fma2(T2w, Pz1, wT2);

                if (kk < 3) {   // kk=3 can never satisfy kk<no (no<=3)
                    const unsigned long long wF2 = (kk < no) ? wT2 : 0ull;
                    fma2(F01, Pxy, wF2); fma2(F2w, Pz1, wF2);
                }
                const unsigned long long wS2 = (kk == no) ? wT2 : 0ull;
                fma2(S01, Pxy, wS2); fma2(S2w, Pz1, wS2);
            }
        }
    }

    float aT0,aT1,aT2,aT3, aF0,aF1,aF2,aF3, aS0,aS1,aS2,aS3;
    unpackf2(T01, aT0, aT1); unpackf2(T2w, aT2, aT3);
    unpackf2(F01, aF0, aF1); unpackf2(F2w, aF2, aF3);
    unpackf2(S01, aS0, aS1); unpackf2(S2w, aS2, aS3);

    float aB0 = aT0 - aF0 - aS0;
    float aB1 = aT1 - aF1 - aS1;
    float aB2 = aT2 - aF2 - aS2;
    float aB3 = aT3 - aF3 - aS3;
    // true nonzero bucket weights are >= ~7e-5; subtraction residue <= ~2e-6.
    if (aB3 < 1e-5f) { aB0 = 0.f; aB1 = 0.f; aB2 = 0.f; aB3 = 0.f; }

    // ---- composite: bg, surface, foreground, then white background ----
    const float ib = __fdividef(1.0f, fmaxf(aB3, 1e-10f));
    float o0 = aB0*ib, o1 = aB1*ib, o2 = aB2*ib, o3 = aB3*ib;

    const float is = __fdividef(1.0f, fmaxf(aS3, 1e-10f));
    {
        const float s0 = aS0*is, s1 = aS1*is, s2 = aS2*is, s3 = aS3*is;
        const float om = 1.0f - s3;
        o0 = s0 + om*o0; o1 = s1 + om*o1; o2 = s2 + om*o2; o3 = s3 + om*o3;
    }
    const float iff = __fdividef(1.0f, fmaxf(aF3, 1e-10f));
    {
        const float f0 = aF0*iff, f1 = aF1*iff, f2 = aF2*iff, f3 = aF3*iff;
        const float om = 1.0f - f3;
        o0 = f0 + om*o0; o1 = f1 + om*o1; o2 = f2 + om*o2; o3 = f3 + om*o3;
    }
    const float bgm = 1.0f - o3;
    const int pix = (n * cfg::HH + (y0 + ty)) * cfg::WW + (x0 + tx);
    reinterpret_cast<float4*>(out)[pix] =
        make_float4(o0 + bgm, o1 + bgm, o2 + bgm, o3);
}

// ---------------------------------------------------------------------------
extern "C" void kernel_launch(void* const* d_in, const int* in_sizes, int n_in,
                              void* d_out, int out_size)
{
    const float* texels  = (const float*)d_in[0];
    const float* normals = (const float*)d_in[1];
    const float* pcam    = (const float*)d_in[2];
    const float* screen  = (const float*)d_in[3];
    const float* qdepth  = (const float*)d_in[4];
    const void*  mask    = d_in[5];
    const float* Lp      = (const float*)d_in[6];
    const float* la      = (const float*)d_in[7];
    const float* ld      = (const float*)d_in[8];
    const float* ls      = (const float*)d_in[9];
    const float* Cp      = (const float*)d_in[10];
    const float* ma      = (const float*)d_in[11];
    const float* md      = (const float*)d_in[12];
    const float* ms      = (const float*)d_in[13];
    float* out = (float*)d_out;

    dim3 blk(256, 1, 1);
    dim3 grd(cfg::WW / cfg::TW, cfg::HH / cfg::TH, cfg::NB);  // 1024 blocks
    fused_kernel<<<grd, blk>>>(texels, normals, pcam, screen, qdepth, mask,
                               Lp, la, ld, ls, Cp, ma, md, ms, out);
}